// round 14
// baseline (speedup 1.0000x reference)
#include <cuda_runtime.h>

#define H_DIM 128
#define W_DIM 128
#define C_DIM 64
#define NTHREADS 512
#define LW 68              // local field width: 64-wide tile + 2 halo each side

// Folded parameters (written by prep_kernel, read by diffusion_kernel)
__device__ float d_wf[4 * 9 * 64];   // conv weights * bn_scale (Dx/Dy also *0.4)
__device__ float d_bf[4 * 64];       // folded biases
__device__ float d_oscale[64];       // output BN scale
__device__ float d_obias[64];        // output BN bias

__global__ void prep_kernel(const float* __restrict__ kg,  const float* __restrict__ kg1,
                            const float* __restrict__ kDx, const float* __restrict__ kDy,
                            const float* __restrict__ bng, const float* __restrict__ bng1,
                            const float* __restrict__ bnDx,const float* __restrict__ bnDy,
                            const float* __restrict__ bn_out)
{
    int c = threadIdx.x;
    if (c >= 64) return;
    const float* ks[4] = {kg, kg1, kDx, kDy};
    const float* bs[4] = {bng, bng1, bnDx, bnDy};
    #pragma unroll
    for (int k = 0; k < 4; k++) {
        float mult  = (k >= 2) ? 0.4f : 1.0f;   // fold 2*DT into Dx/Dy paths
        float gamma = bs[k][c];
        float beta  = bs[k][64 + c];
        float mean  = bs[k][128 + c];
        float var   = bs[k][192 + c];
        float sc = gamma * rsqrtf(var + 1e-3f) * mult;
        #pragma unroll
        for (int t = 0; t < 9; t++)
            d_wf[(k * 9 + t) * 64 + c] = ks[k][t * 64 + c] * sc;
        d_bf[k * 64 + c] = mult * beta - mean * sc;
    }
    float gamma = bn_out[c], beta = bn_out[64 + c], mean = bn_out[128 + c], var = bn_out[192 + c];
    float sc = gamma * rsqrtf(var + 1e-3f);
    d_oscale[c] = sc;
    d_obias[c]  = beta - mean * sc;
}

// One PDE step for a single channel. bx = 2*Bx, by = 2*By.
__device__ __forceinline__ float pde_ch(float g, float gm, float gp,
                                        float g1, float g1m, float g1p,
                                        float bx, float by, float f,
                                        float h, float hwm, float hwp,
                                        float hcm, float hcp)
{
    float D  = __fdividef(1.0f, 1.0f + bx + by);
    float e  = -0.2f * D * ((gm - gp) + (g1m - g1p));  // -2*D*E
    float am = D * (bx - 0.2f * g);
    float ap = D * (bx + 0.2f * g);
    float bm = D * (by - 0.2f * g1);
    float bp = D * (by + 0.2f * g1);
    float T  = D * (1.4f - bx - by) * f;               // h0 == f both iterations
    return T + e * h + am * hwm + ap * hwp + bm * hcm + bp * hcp;
}

__device__ __forceinline__ float4 pde_calc(
    const float* __restrict__ sm_g,  const float* __restrict__ sm_g1,
    const float* __restrict__ sm_bx, const float* __restrict__ sm_by,
    int idx, int cb, float4 fc,
    float4 hc, float4 hm, float4 hp, float h_l, float h_r)
{
    const float4 g_c = *(const float4*)(sm_g  + idx * C_DIM + cb);
    const float4 g_m = *(const float4*)(sm_g  + (idx - 1) * C_DIM + cb);
    const float4 g_p = *(const float4*)(sm_g  + (idx + 1) * C_DIM + cb);
    const float4 q_c = *(const float4*)(sm_g1 + idx * C_DIM + cb);
    const float  q_l = sm_g1[idx * C_DIM + ((cb + 63) & 63)];
    const float  q_r = sm_g1[idx * C_DIM + ((cb + 4)  & 63)];
    const float4 bx  = *(const float4*)(sm_bx + idx * C_DIM + cb);
    const float4 by  = *(const float4*)(sm_by + idx * C_DIM + cb);

    float4 r;
    r.x = pde_ch(g_c.x, g_m.x, g_p.x, q_c.x, q_l,   q_c.y, bx.x, by.x, fc.x, hc.x, hm.x, hp.x, h_l,  hc.y);
    r.y = pde_ch(g_c.y, g_m.y, g_p.y, q_c.y, q_c.x, q_c.z, bx.y, by.y, fc.y, hc.y, hm.y, hp.y, hc.x, hc.z);
    r.z = pde_ch(g_c.z, g_m.z, g_p.z, q_c.z, q_c.y, q_c.w, bx.z, by.z, fc.z, hc.z, hm.z, hp.z, hc.y, hc.w);
    r.w = pde_ch(g_c.w, g_m.w, g_p.w, q_c.w, q_c.z, q_r,   bx.w, by.w, fc.w, hc.w, hm.w, hp.w, hc.z, h_r);
    return r;
}

__device__ __forceinline__ float4 relu4(float4 a)
{
    a.x = fmaxf(a.x, 0.f); a.y = fmaxf(a.y, 0.f);
    a.z = fmaxf(a.z, 0.f); a.w = fmaxf(a.w, 0.f);
    return a;
}

__global__ void __launch_bounds__(NTHREADS, 2)
diffusion_kernel(const float* __restrict__ s0, float* __restrict__ out)
{
    extern __shared__ float smem[];
    float* sm_g  = smem;                    // LW*64 = 4352 floats each
    float* sm_g1 = smem + 1 * LW * C_DIM;
    float* sm_bx = smem + 2 * LW * C_DIM;   // 2*Bx
    float* sm_by = smem + 3 * LW * C_DIM;   // 2*By
    float* sm_h  = smem + 4 * LW * C_DIM;
    float* sm_w  = smem + 5 * LW * C_DIM;   // 2304 folded weights
    float* sm_b  = sm_w + 2304;             // 256 biases
    float* sm_os = sm_b + 256;              // 64
    float* sm_ob = sm_os + 64;              // 64

    const int tid   = threadIdx.x;
    const int h0    = blockIdx.x;           // row
    const int wbase = blockIdx.y * 64;      // w tile origin
    const int b     = blockIdx.z;           // batch
    const int cb    = (tid & 15) * 4;       // channel base (4 channels)
    const int wt    = tid >> 4;             // strip / pair id 0..31

    const float* fimg = s0 + (size_t)b * (H_DIM * W_DIM * C_DIM);
    const float* frow = fimg + (size_t)h0 * (W_DIM * C_DIM);

    // Stage folded params
    for (int i = tid; i < 2304; i += NTHREADS) sm_w[i] = d_wf[i];
    for (int i = tid; i < 256;  i += NTHREADS) sm_b[i] = d_bf[i];
    if (tid < 64) { sm_os[tid] = d_oscale[tid]; sm_ob[tid] = d_obias[tid]; }
    __syncthreads();

    // ---- Fused conv: ONE pass over inputs computes g, g1, 2Bx, 2By.
    // Each thread produces 2 adjacent field positions (a "pair") with a
    // sliding 2-column register window: 3 rows x 4 columns of input loads.
    // 34 pairs (68 field positions); pairs 32,33 done by wt 0,1 in round 1.
    #pragma unroll 1
    for (int r = 0; r < 2; r++) {
        if (r == 1 && wt >= 2) break;
        const int base = 2 * (wt + 32 * r);            // field idx of first output
        const int w0   = (wbase + base - 2) & (W_DIM - 1);  // true w (even, so pair never wraps)

        float4 a0_0, a0_1, a0_2, a0_3;   // outputs at w0
        float4 a1_0, a1_1, a1_2, a1_3;   // outputs at w0+1
        {
            float4 b0 = *(const float4*)(sm_b + 0 * 64 + cb);
            float4 b1 = *(const float4*)(sm_b + 1 * 64 + cb);
            float4 b2 = *(const float4*)(sm_b + 2 * 64 + cb);
            float4 b3 = *(const float4*)(sm_b + 3 * 64 + cb);
            a0_0 = b0; a1_0 = b0; a0_1 = b1; a1_1 = b1;
            a0_2 = b2; a1_2 = b2; a0_3 = b3; a1_3 = b3;
        }
        #pragma unroll
        for (int kh = 0; kh < 3; kh++) {
            const int hh = h0 + kh - 1;
            if ((unsigned)hh >= H_DIM) continue;       // zero pad in H
            const float* rp = fimg + (size_t)hh * (W_DIM * C_DIM) + cb;

            // columns: true w = w0-1+j, j=0..3; pad at true W boundaries
            float4 xa = (w0 > 0) ? __ldg((const float4*)(rp + (w0 - 1) * C_DIM))
                                 : make_float4(0.f, 0.f, 0.f, 0.f);
            float4 xb = __ldg((const float4*)(rp + w0 * C_DIM));
            #pragma unroll
            for (int kw = 0; kw < 3; kw++) {
                const float* wp_ = sm_w + (kh * 3 + kw) * 64 + cb;
                {
                    float4 w0v = *(const float4*)(wp_);
                    float4 w1v = *(const float4*)(wp_ + 576);
                    a0_0.x += xa.x * w0v.x; a0_0.y += xa.y * w0v.y;
                    a0_0.z += xa.z * w0v.z; a0_0.w += xa.w * w0v.w;
                    a1_0.x += xb.x * w0v.x; a1_0.y += xb.y * w0v.y;
                    a1_0.z += xb.z * w0v.z; a1_0.w += xb.w * w0v.w;
                    a0_1.x += xa.x * w1v.x; a0_1.y += xa.y * w1v.y;
                    a0_1.z += xa.z * w1v.z; a0_1.w += xa.w * w1v.w;
                    a1_1.x += xb.x * w1v.x; a1_1.y += xb.y * w1v.y;
                    a1_1.z += xb.z * w1v.z; a1_1.w += xb.w * w1v.w;
                }
                {
                    float4 w2v = *(const float4*)(wp_ + 2 * 576);
                    float4 w3v = *(const float4*)(wp_ + 3 * 576);
                    a0_2.x += xa.x * w2v.x; a0_2.y += xa.y * w2v.y;
                    a0_2.z += xa.z * w2v.z; a0_2.w += xa.w * w2v.w;
                    a1_2.x += xb.x * w2v.x; a1_2.y += xb.y * w2v.y;
                    a1_2.z += xb.z * w2v.z; a1_2.w += xb.w * w2v.w;
                    a0_3.x += xa.x * w3v.x; a0_3.y += xa.y * w3v.y;
                    a0_3.z += xa.z * w3v.z; a0_3.w += xa.w * w3v.w;
                    a1_3.x += xb.x * w3v.x; a1_3.y += xb.y * w3v.y;
                    a1_3.z += xb.z * w3v.z; a1_3.w += xb.w * w3v.w;
                }
                if (kw < 2) {                          // slide window
                    xa = xb;
                    const int wn = w0 + kw + 1;        // col kw+2: true w
                    xb = (wn < W_DIM) ? __ldg((const float4*)(rp + wn * C_DIM))
                                      : make_float4(0.f, 0.f, 0.f, 0.f);
                }
            }
        }
        const int o0 = base * C_DIM + cb, o1 = (base + 1) * C_DIM + cb;
        *(float4*)(sm_g  + o0) = relu4(a0_0); *(float4*)(sm_g  + o1) = relu4(a1_0);
        *(float4*)(sm_g1 + o0) = relu4(a0_1); *(float4*)(sm_g1 + o1) = relu4(a1_1);
        *(float4*)(sm_bx + o0) = relu4(a0_2); *(float4*)(sm_bx + o1) = relu4(a1_2);
        *(float4*)(sm_by + o0) = relu4(a0_3); *(float4*)(sm_by + o1) = relu4(a1_3);
    }
    __syncthreads();

    // ---- PDE iteration 1: h = f (read straight from gmem, L1-hot), write h1 ----
    for (int idx = 1 + wt; idx < LW - 1; idx += 32) {
        int wc = (wbase + idx - 2) & (W_DIM - 1);
        int wm = (wc + W_DIM - 1) & (W_DIM - 1);
        int wp = (wc + 1) & (W_DIM - 1);
        float4 fc = __ldg((const float4*)(frow + wc * C_DIM + cb));
        float4 hm = __ldg((const float4*)(frow + wm * C_DIM + cb));
        float4 hp = __ldg((const float4*)(frow + wp * C_DIM + cb));
        float h_l = __ldg(frow + wc * C_DIM + ((cb + 63) & 63));
        float h_r = __ldg(frow + wc * C_DIM + ((cb + 4)  & 63));
        float4 h1 = pde_calc(sm_g, sm_g1, sm_bx, sm_by, idx, cb, fc, fc, hm, hp, h_l, h_r);
        *(float4*)(sm_h + idx * C_DIM + cb) = h1;
    }
    __syncthreads();

    // ---- PDE iteration 2 + output BN + ReLU, fused store ----
    float4 osc = *(const float4*)(sm_os + cb);
    float4 obi = *(const float4*)(sm_ob + cb);
    float* orow = out + ((size_t)(b * H_DIM + h0)) * (W_DIM * C_DIM);
    #pragma unroll
    for (int r = 0; r < 2; r++) {
        int idx = 2 + wt + 32 * r;                    // [2, 66): exactly the 64-wide tile
        int wc = (wbase + idx - 2) & (W_DIM - 1);
        float4 fc = __ldg((const float4*)(frow + wc * C_DIM + cb));
        float4 hc = *(const float4*)(sm_h + idx * C_DIM + cb);
        float4 hm = *(const float4*)(sm_h + (idx - 1) * C_DIM + cb);
        float4 hp = *(const float4*)(sm_h + (idx + 1) * C_DIM + cb);
        float h_l = sm_h[idx * C_DIM + ((cb + 63) & 63)];
        float h_r = sm_h[idx * C_DIM + ((cb + 4)  & 63)];
        float4 h2 = pde_calc(sm_g, sm_g1, sm_bx, sm_by, idx, cb, fc, hc, hm, hp, h_l, h_r);
        float4 o;
        o.x = fmaxf(osc.x * h2.x + obi.x, 0.f);
        o.y = fmaxf(osc.y * h2.y + obi.y, 0.f);
        o.z = fmaxf(osc.z * h2.z + obi.z, 0.f);
        o.w = fmaxf(osc.w * h2.w + obi.w, 0.f);
        *(float4*)(orow + wc * C_DIM + cb) = o;
    }
}

extern "C" void kernel_launch(void* const* d_in, const int* in_sizes, int n_in,
                              void* d_out, int out_size)
{
    const float* s0   = (const float*)d_in[0];
    const float* kg   = (const float*)d_in[1];
    const float* kg1  = (const float*)d_in[2];
    const float* kDx  = (const float*)d_in[3];
    const float* kDy  = (const float*)d_in[4];
    const float* bng  = (const float*)d_in[5];
    const float* bng1 = (const float*)d_in[6];
    const float* bnDx = (const float*)d_in[7];
    const float* bnDy = (const float*)d_in[8];
    const float* bnO  = (const float*)d_in[9];
    float* out = (float*)d_out;

    int batch = in_sizes[0] / (H_DIM * W_DIM * C_DIM);

    size_t smem_bytes = (size_t)(5 * LW * C_DIM + 2304 + 256 + 128) * sizeof(float); // 97,792 B
    cudaFuncSetAttribute(diffusion_kernel,
                         cudaFuncAttributeMaxDynamicSharedMemorySize, (int)smem_bytes);

    prep_kernel<<<1, 64>>>(kg, kg1, kDx, kDy, bng, bng1, bnDx, bnDy, bnO);

    dim3 grid(H_DIM, W_DIM / 64, batch);   // (row, w-tile, batch) = 128 x 2 x 16
    diffusion_kernel<<<grid, NTHREADS, smem_bytes>>>(s0, out);
}

// round 16
// speedup vs baseline: 1.0040x; 1.0040x over previous
#include <cuda_runtime.h>

#define H_DIM 128
#define W_DIM 128
#define C_DIM 64
#define NTHREADS 512
#define LW 68              // local field width: 64-wide tile + 2 halo each side

// Folded parameters (written by prep_kernel, read by diffusion_kernel)
__device__ float d_wf[4 * 9 * 64];   // conv weights * bn_scale (Dx/Dy also *0.4)
__device__ float d_bf[4 * 64];       // folded biases
__device__ float d_oscale[64];       // output BN scale
__device__ float d_obias[64];        // output BN bias

__global__ void prep_kernel(const float* __restrict__ kg,  const float* __restrict__ kg1,
                            const float* __restrict__ kDx, const float* __restrict__ kDy,
                            const float* __restrict__ bng, const float* __restrict__ bng1,
                            const float* __restrict__ bnDx,const float* __restrict__ bnDy,
                            const float* __restrict__ bn_out)
{
    int c = threadIdx.x;
    if (c >= 64) return;
    const float* ks[4] = {kg, kg1, kDx, kDy};
    const float* bs[4] = {bng, bng1, bnDx, bnDy};
    #pragma unroll
    for (int k = 0; k < 4; k++) {
        float mult  = (k >= 2) ? 0.4f : 1.0f;   // fold 2*DT into Dx/Dy paths
        float gamma = bs[k][c];
        float beta  = bs[k][64 + c];
        float mean  = bs[k][128 + c];
        float var   = bs[k][192 + c];
        float sc = gamma * rsqrtf(var + 1e-3f) * mult;
        #pragma unroll
        for (int t = 0; t < 9; t++)
            d_wf[(k * 9 + t) * 64 + c] = ks[k][t * 64 + c] * sc;
        d_bf[k * 64 + c] = mult * beta - mean * sc;
    }
    float gamma = bn_out[c], beta = bn_out[64 + c], mean = bn_out[128 + c], var = bn_out[192 + c];
    float sc = gamma * rsqrtf(var + 1e-3f);
    d_oscale[c] = sc;
    d_obias[c]  = beta - mean * sc;
}

// One PDE step for a single channel. bx = 2*Bx, by = 2*By.
__device__ __forceinline__ float pde_ch(float g, float gm, float gp,
                                        float g1, float g1m, float g1p,
                                        float bx, float by, float f,
                                        float h, float hwm, float hwp,
                                        float hcm, float hcp)
{
    float D  = __fdividef(1.0f, 1.0f + bx + by);
    float e  = -0.2f * D * ((gm - gp) + (g1m - g1p));  // -2*D*E
    float am = D * (bx - 0.2f * g);
    float ap = D * (bx + 0.2f * g);
    float bm = D * (by - 0.2f * g1);
    float bp = D * (by + 0.2f * g1);
    float T  = D * (1.4f - bx - by) * f;               // h0 == f both iterations
    return T + e * h + am * hwm + ap * hwp + bm * hcm + bp * hcp;
}

__device__ __forceinline__ float4 pde_calc(
    const float* __restrict__ sm_g,  const float* __restrict__ sm_g1,
    const float* __restrict__ sm_bx, const float* __restrict__ sm_by,
    int idx, int cb, float4 fc,
    float4 hc, float4 hm, float4 hp, float h_l, float h_r)
{
    const float4 g_c = *(const float4*)(sm_g  + idx * C_DIM + cb);
    const float4 g_m = *(const float4*)(sm_g  + (idx - 1) * C_DIM + cb);
    const float4 g_p = *(const float4*)(sm_g  + (idx + 1) * C_DIM + cb);
    const float4 q_c = *(const float4*)(sm_g1 + idx * C_DIM + cb);
    const float  q_l = sm_g1[idx * C_DIM + ((cb + 63) & 63)];
    const float  q_r = sm_g1[idx * C_DIM + ((cb + 4)  & 63)];
    const float4 bx  = *(const float4*)(sm_bx + idx * C_DIM + cb);
    const float4 by  = *(const float4*)(sm_by + idx * C_DIM + cb);

    float4 r;
    r.x = pde_ch(g_c.x, g_m.x, g_p.x, q_c.x, q_l,   q_c.y, bx.x, by.x, fc.x, hc.x, hm.x, hp.x, h_l,  hc.y);
    r.y = pde_ch(g_c.y, g_m.y, g_p.y, q_c.y, q_c.x, q_c.z, bx.y, by.y, fc.y, hc.y, hm.y, hp.y, hc.x, hc.z);
    r.z = pde_ch(g_c.z, g_m.z, g_p.z, q_c.z, q_c.y, q_c.w, bx.z, by.z, fc.z, hc.z, hm.z, hp.z, hc.y, hc.w);
    r.w = pde_ch(g_c.w, g_m.w, g_p.w, q_c.w, q_c.z, q_r,   bx.w, by.w, fc.w, hc.w, hm.w, hp.w, hc.z, h_r);
    return r;
}

__device__ __forceinline__ float4 relu4(float4 a)
{
    a.x = fmaxf(a.x, 0.f); a.y = fmaxf(a.y, 0.f);
    a.z = fmaxf(a.z, 0.f); a.w = fmaxf(a.w, 0.f);
    return a;
}

__global__ void __launch_bounds__(NTHREADS, 2)
diffusion_kernel(const float* __restrict__ s0, float* __restrict__ out)
{
    extern __shared__ float smem[];
    float* sm_g  = smem;                    // LW*64 = 4352 floats each
    float* sm_g1 = smem + 1 * LW * C_DIM;
    float* sm_bx = smem + 2 * LW * C_DIM;   // 2*Bx
    float* sm_by = smem + 3 * LW * C_DIM;   // 2*By
    float* sm_h  = smem + 4 * LW * C_DIM;
    float* sm_w  = smem + 5 * LW * C_DIM;   // 2304 folded weights
    float* sm_b  = sm_w + 2304;             // 256 biases
    float* sm_os = sm_b + 256;              // 64
    float* sm_ob = sm_os + 64;              // 64

    const int tid   = threadIdx.x;
    const int h0    = blockIdx.x;           // row
    const int wbase = blockIdx.y * 64;      // w tile origin
    const int b     = blockIdx.z;           // batch
    const int cb    = (tid & 15) * 4;       // channel base (4 channels)
    const int wt    = tid >> 4;             // strip / pair id 0..31

    const float* fimg = s0 + (size_t)b * (H_DIM * W_DIM * C_DIM);
    const float* frow = fimg + (size_t)h0 * (W_DIM * C_DIM);

    // Stage folded params
    for (int i = tid; i < 2304; i += NTHREADS) sm_w[i] = d_wf[i];
    for (int i = tid; i < 256;  i += NTHREADS) sm_b[i] = d_bf[i];
    if (tid < 64) { sm_os[tid] = d_oscale[tid]; sm_ob[tid] = d_obias[tid]; }
    __syncthreads();

    // ---- Fused conv: ONE pass over inputs computes g, g1, 2Bx, 2By.
    // Each thread produces 2 adjacent field positions (a "pair") with a
    // sliding 2-column register window: 3 rows x 4 columns of input loads.
    // 34 pairs (68 field positions); pairs 32,33 done by wt 0,1 in round 1.
    #pragma unroll 1
    for (int r = 0; r < 2; r++) {
        if (r == 1 && wt >= 2) break;
        const int base = 2 * (wt + 32 * r);            // field idx of first output
        const int w0   = (wbase + base - 2) & (W_DIM - 1);  // true w (even, so pair never wraps)

        float4 a0_0, a0_1, a0_2, a0_3;   // outputs at w0
        float4 a1_0, a1_1, a1_2, a1_3;   // outputs at w0+1
        {
            float4 b0 = *(const float4*)(sm_b + 0 * 64 + cb);
            float4 b1 = *(const float4*)(sm_b + 1 * 64 + cb);
            float4 b2 = *(const float4*)(sm_b + 2 * 64 + cb);
            float4 b3 = *(const float4*)(sm_b + 3 * 64 + cb);
            a0_0 = b0; a1_0 = b0; a0_1 = b1; a1_1 = b1;
            a0_2 = b2; a1_2 = b2; a0_3 = b3; a1_3 = b3;
        }
        #pragma unroll
        for (int kh = 0; kh < 3; kh++) {
            const int hh = h0 + kh - 1;
            if ((unsigned)hh >= H_DIM) continue;       // zero pad in H
            const float* rp = fimg + (size_t)hh * (W_DIM * C_DIM) + cb;

            // columns: true w = w0-1+j, j=0..3; pad at true W boundaries
            float4 xa = (w0 > 0) ? __ldg((const float4*)(rp + (w0 - 1) * C_DIM))
                                 : make_float4(0.f, 0.f, 0.f, 0.f);
            float4 xb = __ldg((const float4*)(rp + w0 * C_DIM));
            #pragma unroll
            for (int kw = 0; kw < 3; kw++) {
                const float* wp_ = sm_w + (kh * 3 + kw) * 64 + cb;
                {
                    float4 w0v = *(const float4*)(wp_);
                    float4 w1v = *(const float4*)(wp_ + 576);
                    a0_0.x += xa.x * w0v.x; a0_0.y += xa.y * w0v.y;
                    a0_0.z += xa.z * w0v.z; a0_0.w += xa.w * w0v.w;
                    a1_0.x += xb.x * w0v.x; a1_0.y += xb.y * w0v.y;
                    a1_0.z += xb.z * w0v.z; a1_0.w += xb.w * w0v.w;
                    a0_1.x += xa.x * w1v.x; a0_1.y += xa.y * w1v.y;
                    a0_1.z += xa.z * w1v.z; a0_1.w += xa.w * w1v.w;
                    a1_1.x += xb.x * w1v.x; a1_1.y += xb.y * w1v.y;
                    a1_1.z += xb.z * w1v.z; a1_1.w += xb.w * w1v.w;
                }
                {
                    float4 w2v = *(const float4*)(wp_ + 2 * 576);
                    float4 w3v = *(const float4*)(wp_ + 3 * 576);
                    a0_2.x += xa.x * w2v.x; a0_2.y += xa.y * w2v.y;
                    a0_2.z += xa.z * w2v.z; a0_2.w += xa.w * w2v.w;
                    a1_2.x += xb.x * w2v.x; a1_2.y += xb.y * w2v.y;
                    a1_2.z += xb.z * w2v.z; a1_2.w += xb.w * w2v.w;
                    a0_3.x += xa.x * w3v.x; a0_3.y += xa.y * w3v.y;
                    a0_3.z += xa.z * w3v.z; a0_3.w += xa.w * w3v.w;
                    a1_3.x += xb.x * w3v.x; a1_3.y += xb.y * w3v.y;
                    a1_3.z += xb.z * w3v.z; a1_3.w += xb.w * w3v.w;
                }
                if (kw < 2) {                          // slide window
                    xa = xb;
                    const int wn = w0 + kw + 1;        // col kw+2: true w
                    xb = (wn < W_DIM) ? __ldg((const float4*)(rp + wn * C_DIM))
                                      : make_float4(0.f, 0.f, 0.f, 0.f);
                }
            }
        }
        const int o0 = base * C_DIM + cb, o1 = (base + 1) * C_DIM + cb;
        *(float4*)(sm_g  + o0) = relu4(a0_0); *(float4*)(sm_g  + o1) = relu4(a1_0);
        *(float4*)(sm_g1 + o0) = relu4(a0_1); *(float4*)(sm_g1 + o1) = relu4(a1_1);
        *(float4*)(sm_bx + o0) = relu4(a0_2); *(float4*)(sm_bx + o1) = relu4(a1_2);
        *(float4*)(sm_by + o0) = relu4(a0_3); *(float4*)(sm_by + o1) = relu4(a1_3);
    }
    __syncthreads();

    // ---- PDE iteration 1: h = f (read straight from gmem, L1-hot), write h1 ----
    for (int idx = 1 + wt; idx < LW - 1; idx += 32) {
        int wc = (wbase + idx - 2) & (W_DIM - 1);
        int wm = (wc + W_DIM - 1) & (W_DIM - 1);
        int wp = (wc + 1) & (W_DIM - 1);
        float4 fc = __ldg((const float4*)(frow + wc * C_DIM + cb));
        float4 hm = __ldg((const float4*)(frow + wm * C_DIM + cb));
        float4 hp = __ldg((const float4*)(frow + wp * C_DIM + cb));
        float h_l = __ldg(frow + wc * C_DIM + ((cb + 63) & 63));
        float h_r = __ldg(frow + wc * C_DIM + ((cb + 4)  & 63));
        float4 h1 = pde_calc(sm_g, sm_g1, sm_bx, sm_by, idx, cb, fc, fc, hm, hp, h_l, h_r);
        *(float4*)(sm_h + idx * C_DIM + cb) = h1;
    }
    __syncthreads();

    // ---- PDE iteration 2 + output BN + ReLU, fused store ----
    float4 osc = *(const float4*)(sm_os + cb);
    float4 obi = *(const float4*)(sm_ob + cb);
    float* orow = out + ((size_t)(b * H_DIM + h0)) * (W_DIM * C_DIM);
    #pragma unroll
    for (int r = 0; r < 2; r++) {
        int idx = 2 + wt + 32 * r;                    // [2, 66): exactly the 64-wide tile
        int wc = (wbase + idx - 2) & (W_DIM - 1);
        float4 fc = __ldg((const float4*)(frow + wc * C_DIM + cb));
        float4 hc = *(const float4*)(sm_h + idx * C_DIM + cb);
        float4 hm = *(const float4*)(sm_h + (idx - 1) * C_DIM + cb);
        float4 hp = *(const float4*)(sm_h + (idx + 1) * C_DIM + cb);
        float h_l = sm_h[idx * C_DIM + ((cb + 63) & 63)];
        float h_r = sm_h[idx * C_DIM + ((cb + 4)  & 63)];
        float4 h2 = pde_calc(sm_g, sm_g1, sm_bx, sm_by, idx, cb, fc, hc, hm, hp, h_l, h_r);
        float4 o;
        o.x = fmaxf(osc.x * h2.x + obi.x, 0.f);
        o.y = fmaxf(osc.y * h2.y + obi.y, 0.f);
        o.z = fmaxf(osc.z * h2.z + obi.z, 0.f);
        o.w = fmaxf(osc.w * h2.w + obi.w, 0.f);
        *(float4*)(orow + wc * C_DIM + cb) = o;
    }
}

extern "C" void kernel_launch(void* const* d_in, const int* in_sizes, int n_in,
                              void* d_out, int out_size)
{
    const float* s0   = (const float*)d_in[0];
    const float* kg   = (const float*)d_in[1];
    const float* kg1  = (const float*)d_in[2];
    const float* kDx  = (const float*)d_in[3];
    const float* kDy  = (const float*)d_in[4];
    const float* bng  = (const float*)d_in[5];
    const float* bng1 = (const float*)d_in[6];
    const float* bnDx = (const float*)d_in[7];
    const float* bnDy = (const float*)d_in[8];
    const float* bnO  = (const float*)d_in[9];
    float* out = (float*)d_out;

    int batch = in_sizes[0] / (H_DIM * W_DIM * C_DIM);

    size_t smem_bytes = (size_t)(5 * LW * C_DIM + 2304 + 256 + 128) * sizeof(float); // 97,792 B
    cudaFuncSetAttribute(diffusion_kernel,
                         cudaFuncAttributeMaxDynamicSharedMemorySize, (int)smem_bytes);

    prep_kernel<<<1, 64>>>(kg, kg1, kDx, kDy, bng, bng1, bnDx, bnDy, bnO);

    dim3 grid(H_DIM, W_DIM / 64, batch);   // (row, w-tile, batch) = 128 x 2 x 16
    diffusion_kernel<<<grid, NTHREADS, smem_bytes>>>(s0, out);
}

// round 17
// speedup vs baseline: 1.0060x; 1.0020x over previous
#include <cuda_runtime.h>

#define H_DIM 128
#define W_DIM 128
#define C_DIM 64
#define NTHREADS 512
#define LW 68              // local field width: 64-wide tile + 2 halo each side

// Folded parameters (written by prep_kernel, read by diffusion_kernel)
__device__ float d_wf[4 * 9 * 64];   // conv weights * bn_scale (Dx/Dy also *0.4)
__device__ float d_bf[4 * 64];       // folded biases
__device__ float d_oscale[64];       // output BN scale
__device__ float d_obias[64];        // output BN bias

__global__ void prep_kernel(const float* __restrict__ kg,  const float* __restrict__ kg1,
                            const float* __restrict__ kDx, const float* __restrict__ kDy,
                            const float* __restrict__ bng, const float* __restrict__ bng1,
                            const float* __restrict__ bnDx,const float* __restrict__ bnDy,
                            const float* __restrict__ bn_out)
{
    int c = threadIdx.x;
    if (c >= 64) return;
    const float* ks[4] = {kg, kg1, kDx, kDy};
    const float* bs[4] = {bng, bng1, bnDx, bnDy};
    #pragma unroll
    for (int k = 0; k < 4; k++) {
        float mult  = (k >= 2) ? 0.4f : 1.0f;   // fold 2*DT into Dx/Dy paths
        float gamma = bs[k][c];
        float beta  = bs[k][64 + c];
        float mean  = bs[k][128 + c];
        float var   = bs[k][192 + c];
        float sc = gamma * rsqrtf(var + 1e-3f) * mult;
        #pragma unroll
        for (int t = 0; t < 9; t++)
            d_wf[(k * 9 + t) * 64 + c] = ks[k][t * 64 + c] * sc;
        d_bf[k * 64 + c] = mult * beta - mean * sc;
    }
    float gamma = bn_out[c], beta = bn_out[64 + c], mean = bn_out[128 + c], var = bn_out[192 + c];
    float sc = gamma * rsqrtf(var + 1e-3f);
    d_oscale[c] = sc;
    d_obias[c]  = beta - mean * sc;
}

// One PDE step for a single channel. bx = 2*Bx, by = 2*By.
__device__ __forceinline__ float pde_ch(float g, float gm, float gp,
                                        float g1, float g1m, float g1p,
                                        float bx, float by, float f,
                                        float h, float hwm, float hwp,
                                        float hcm, float hcp)
{
    float D  = __fdividef(1.0f, 1.0f + bx + by);
    float e  = -0.2f * D * ((gm - gp) + (g1m - g1p));  // -2*D*E
    float am = D * (bx - 0.2f * g);
    float ap = D * (bx + 0.2f * g);
    float bm = D * (by - 0.2f * g1);
    float bp = D * (by + 0.2f * g1);
    float T  = D * (1.4f - bx - by) * f;               // h0 == f both iterations
    return T + e * h + am * hwm + ap * hwp + bm * hcm + bp * hcp;
}

__device__ __forceinline__ float4 pde_calc(
    const float* __restrict__ sm_g,  const float* __restrict__ sm_g1,
    const float* __restrict__ sm_bx, const float* __restrict__ sm_by,
    int idx, int cb, float4 fc,
    float4 hc, float4 hm, float4 hp, float h_l, float h_r)
{
    const float4 g_c = *(const float4*)(sm_g  + idx * C_DIM + cb);
    const float4 g_m = *(const float4*)(sm_g  + (idx - 1) * C_DIM + cb);
    const float4 g_p = *(const float4*)(sm_g  + (idx + 1) * C_DIM + cb);
    const float4 q_c = *(const float4*)(sm_g1 + idx * C_DIM + cb);
    const float  q_l = sm_g1[idx * C_DIM + ((cb + 63) & 63)];
    const float  q_r = sm_g1[idx * C_DIM + ((cb + 4)  & 63)];
    const float4 bx  = *(const float4*)(sm_bx + idx * C_DIM + cb);
    const float4 by  = *(const float4*)(sm_by + idx * C_DIM + cb);

    float4 r;
    r.x = pde_ch(g_c.x, g_m.x, g_p.x, q_c.x, q_l,   q_c.y, bx.x, by.x, fc.x, hc.x, hm.x, hp.x, h_l,  hc.y);
    r.y = pde_ch(g_c.y, g_m.y, g_p.y, q_c.y, q_c.x, q_c.z, bx.y, by.y, fc.y, hc.y, hm.y, hp.y, hc.x, hc.z);
    r.z = pde_ch(g_c.z, g_m.z, g_p.z, q_c.z, q_c.y, q_c.w, bx.z, by.z, fc.z, hc.z, hm.z, hp.z, hc.y, hc.w);
    r.w = pde_ch(g_c.w, g_m.w, g_p.w, q_c.w, q_c.z, q_r,   bx.w, by.w, fc.w, hc.w, hm.w, hp.w, hc.z, h_r);
    return r;
}

__device__ __forceinline__ float4 relu4(float4 a)
{
    a.x = fmaxf(a.x, 0.f); a.y = fmaxf(a.y, 0.f);
    a.z = fmaxf(a.z, 0.f); a.w = fmaxf(a.w, 0.f);
    return a;
}

__global__ void __launch_bounds__(NTHREADS, 2)
diffusion_kernel(const float* __restrict__ s0, float* __restrict__ out)
{
    extern __shared__ float smem[];
    float* sm_g  = smem;                    // LW*64 = 4352 floats each
    float* sm_g1 = smem + 1 * LW * C_DIM;
    float* sm_bx = smem + 2 * LW * C_DIM;   // 2*Bx
    float* sm_by = smem + 3 * LW * C_DIM;   // 2*By
    float* sm_h  = smem + 4 * LW * C_DIM;
    float* sm_w  = smem + 5 * LW * C_DIM;   // 2304 folded weights
    float* sm_b  = sm_w + 2304;             // 256 biases
    float* sm_os = sm_b + 256;              // 64
    float* sm_ob = sm_os + 64;              // 64

    const int tid   = threadIdx.x;
    const int h0    = blockIdx.x;           // row
    const int wbase = blockIdx.y * 64;      // w tile origin
    const int b     = blockIdx.z;           // batch
    const int cb    = (tid & 15) * 4;       // channel base (4 channels)
    const int wt    = tid >> 4;             // strip / pair id 0..31

    const float* fimg = s0 + (size_t)b * (H_DIM * W_DIM * C_DIM);
    const float* frow = fimg + (size_t)h0 * (W_DIM * C_DIM);

    // Stage folded params
    for (int i = tid; i < 2304; i += NTHREADS) sm_w[i] = d_wf[i];
    for (int i = tid; i < 256;  i += NTHREADS) sm_b[i] = d_bf[i];
    if (tid < 64) { sm_os[tid] = d_oscale[tid]; sm_ob[tid] = d_obias[tid]; }
    __syncthreads();

    // ---- Fused conv: ONE pass over inputs computes g, g1, 2Bx, 2By.
    // Each thread produces 2 adjacent field positions (a "pair") with a
    // sliding 2-column register window: 3 rows x 4 columns of input loads.
    // 34 pairs (68 field positions); pairs 32,33 done by wt 0,1 in round 1.
    #pragma unroll 1
    for (int r = 0; r < 2; r++) {
        if (r == 1 && wt >= 2) break;
        const int base = 2 * (wt + 32 * r);            // field idx of first output
        const int w0   = (wbase + base - 2) & (W_DIM - 1);  // true w (even, so pair never wraps)

        float4 a0_0, a0_1, a0_2, a0_3;   // outputs at w0
        float4 a1_0, a1_1, a1_2, a1_3;   // outputs at w0+1
        {
            float4 b0 = *(const float4*)(sm_b + 0 * 64 + cb);
            float4 b1 = *(const float4*)(sm_b + 1 * 64 + cb);
            float4 b2 = *(const float4*)(sm_b + 2 * 64 + cb);
            float4 b3 = *(const float4*)(sm_b + 3 * 64 + cb);
            a0_0 = b0; a1_0 = b0; a0_1 = b1; a1_1 = b1;
            a0_2 = b2; a1_2 = b2; a0_3 = b3; a1_3 = b3;
        }
        #pragma unroll
        for (int kh = 0; kh < 3; kh++) {
            const int hh = h0 + kh - 1;
            if ((unsigned)hh >= H_DIM) continue;       // zero pad in H
            const float* rp = fimg + (size_t)hh * (W_DIM * C_DIM) + cb;

            // columns: true w = w0-1+j, j=0..3; pad at true W boundaries
            float4 xa = (w0 > 0) ? __ldg((const float4*)(rp + (w0 - 1) * C_DIM))
                                 : make_float4(0.f, 0.f, 0.f, 0.f);
            float4 xb = __ldg((const float4*)(rp + w0 * C_DIM));
            #pragma unroll
            for (int kw = 0; kw < 3; kw++) {
                const float* wp_ = sm_w + (kh * 3 + kw) * 64 + cb;
                {
                    float4 w0v = *(const float4*)(wp_);
                    float4 w1v = *(const float4*)(wp_ + 576);
                    a0_0.x += xa.x * w0v.x; a0_0.y += xa.y * w0v.y;
                    a0_0.z += xa.z * w0v.z; a0_0.w += xa.w * w0v.w;
                    a1_0.x += xb.x * w0v.x; a1_0.y += xb.y * w0v.y;
                    a1_0.z += xb.z * w0v.z; a1_0.w += xb.w * w0v.w;
                    a0_1.x += xa.x * w1v.x; a0_1.y += xa.y * w1v.y;
                    a0_1.z += xa.z * w1v.z; a0_1.w += xa.w * w1v.w;
                    a1_1.x += xb.x * w1v.x; a1_1.y += xb.y * w1v.y;
                    a1_1.z += xb.z * w1v.z; a1_1.w += xb.w * w1v.w;
                }
                {
                    float4 w2v = *(const float4*)(wp_ + 2 * 576);
                    float4 w3v = *(const float4*)(wp_ + 3 * 576);
                    a0_2.x += xa.x * w2v.x; a0_2.y += xa.y * w2v.y;
                    a0_2.z += xa.z * w2v.z; a0_2.w += xa.w * w2v.w;
                    a1_2.x += xb.x * w2v.x; a1_2.y += xb.y * w2v.y;
                    a1_2.z += xb.z * w2v.z; a1_2.w += xb.w * w2v.w;
                    a0_3.x += xa.x * w3v.x; a0_3.y += xa.y * w3v.y;
                    a0_3.z += xa.z * w3v.z; a0_3.w += xa.w * w3v.w;
                    a1_3.x += xb.x * w3v.x; a1_3.y += xb.y * w3v.y;
                    a1_3.z += xb.z * w3v.z; a1_3.w += xb.w * w3v.w;
                }
                if (kw < 2) {                          // slide window
                    xa = xb;
                    const int wn = w0 + kw + 1;        // col kw+2: true w
                    xb = (wn < W_DIM) ? __ldg((const float4*)(rp + wn * C_DIM))
                                      : make_float4(0.f, 0.f, 0.f, 0.f);
                }
            }
        }
        const int o0 = base * C_DIM + cb, o1 = (base + 1) * C_DIM + cb;
        *(float4*)(sm_g  + o0) = relu4(a0_0); *(float4*)(sm_g  + o1) = relu4(a1_0);
        *(float4*)(sm_g1 + o0) = relu4(a0_1); *(float4*)(sm_g1 + o1) = relu4(a1_1);
        *(float4*)(sm_bx + o0) = relu4(a0_2); *(float4*)(sm_bx + o1) = relu4(a1_2);
        *(float4*)(sm_by + o0) = relu4(a0_3); *(float4*)(sm_by + o1) = relu4(a1_3);
    }
    __syncthreads();

    // ---- PDE iteration 1: h = f (read straight from gmem, L1-hot), write h1 ----
    for (int idx = 1 + wt; idx < LW - 1; idx += 32) {
        int wc = (wbase + idx - 2) & (W_DIM - 1);
        int wm = (wc + W_DIM - 1) & (W_DIM - 1);
        int wp = (wc + 1) & (W_DIM - 1);
        float4 fc = __ldg((const float4*)(frow + wc * C_DIM + cb));
        float4 hm = __ldg((const float4*)(frow + wm * C_DIM + cb));
        float4 hp = __ldg((const float4*)(frow + wp * C_DIM + cb));
        float h_l = __ldg(frow + wc * C_DIM + ((cb + 63) & 63));
        float h_r = __ldg(frow + wc * C_DIM + ((cb + 4)  & 63));
        float4 h1 = pde_calc(sm_g, sm_g1, sm_bx, sm_by, idx, cb, fc, fc, hm, hp, h_l, h_r);
        *(float4*)(sm_h + idx * C_DIM + cb) = h1;
    }
    __syncthreads();

    // ---- PDE iteration 2 + output BN + ReLU, fused store ----
    float4 osc = *(const float4*)(sm_os + cb);
    float4 obi = *(const float4*)(sm_ob + cb);
    float* orow = out + ((size_t)(b * H_DIM + h0)) * (W_DIM * C_DIM);
    #pragma unroll
    for (int r = 0; r < 2; r++) {
        int idx = 2 + wt + 32 * r;                    // [2, 66): exactly the 64-wide tile
        int wc = (wbase + idx - 2) & (W_DIM - 1);
        float4 fc = __ldg((const float4*)(frow + wc * C_DIM + cb));
        float4 hc = *(const float4*)(sm_h + idx * C_DIM + cb);
        float4 hm = *(const float4*)(sm_h + (idx - 1) * C_DIM + cb);
        float4 hp = *(const float4*)(sm_h + (idx + 1) * C_DIM + cb);
        float h_l = sm_h[idx * C_DIM + ((cb + 63) & 63)];
        float h_r = sm_h[idx * C_DIM + ((cb + 4)  & 63)];
        float4 h2 = pde_calc(sm_g, sm_g1, sm_bx, sm_by, idx, cb, fc, hc, hm, hp, h_l, h_r);
        float4 o;
        o.x = fmaxf(osc.x * h2.x + obi.x, 0.f);
        o.y = fmaxf(osc.y * h2.y + obi.y, 0.f);
        o.z = fmaxf(osc.z * h2.z + obi.z, 0.f);
        o.w = fmaxf(osc.w * h2.w + obi.w, 0.f);
        *(float4*)(orow + wc * C_DIM + cb) = o;
    }
}

extern "C" void kernel_launch(void* const* d_in, const int* in_sizes, int n_in,
                              void* d_out, int out_size)
{
    const float* s0   = (const float*)d_in[0];
    const float* kg   = (const float*)d_in[1];
    const float* kg1  = (const float*)d_in[2];
    const float* kDx  = (const float*)d_in[3];
    const float* kDy  = (const float*)d_in[4];
    const float* bng  = (const float*)d_in[5];
    const float* bng1 = (const float*)d_in[6];
    const float* bnDx = (const float*)d_in[7];
    const float* bnDy = (const float*)d_in[8];
    const float* bnO  = (const float*)d_in[9];
    float* out = (float*)d_out;

    int batch = in_sizes[0] / (H_DIM * W_DIM * C_DIM);

    size_t smem_bytes = (size_t)(5 * LW * C_DIM + 2304 + 256 + 128) * sizeof(float); // 97,792 B
    cudaFuncSetAttribute(diffusion_kernel,
                         cudaFuncAttributeMaxDynamicSharedMemorySize, (int)smem_bytes);

    prep_kernel<<<1, 64>>>(kg, kg1, kDx, kDy, bng, bng1, bnDx, bnDy, bnO);

    dim3 grid(H_DIM, W_DIM / 64, batch);   // (row, w-tile, batch) = 128 x 2 x 16
    diffusion_kernel<<<grid, NTHREADS, smem_bytes>>>(s0, out);
}